// round 5
// baseline (speedup 1.0000x reference)
#include <cuda_runtime.h>
#include <math.h>

typedef unsigned long long u64;

#define DIM_E 256
#define NH1   32
#define NH2   16
#define MAX_D 1024
#define MAX_N 131072

#define BT    128            // threads in op_main
#define OPB   512            // ops per block (M=4 per thread)
#define KT    16             // k per tile
#define NTILE (DIM_E / KT)   // 16
#define PL    517            // smem x plane stride in float4 (conflict-free)
#define MAX_BLK 1024

// dynamic smem layout for op_main
#define OFF_W1   0           // 4096 u64  = 32768 B
#define OFF_W2   32768       // 256 u64   = 2048 B
#define OFF_MISC 34816       // 96 floats = 384 B
#define OFF_X    35200       // 2 * 4*PL float4 = 66176 B
#define SMEM_SZ  (35200 + 2 * 4 * PL * 16)

// ---------------- device scratch ----------------
__device__ float g_zsum_op[NH1];
__device__ float g_zsum_pr[NH1];
__device__ float g_ydag_op[MAX_D * NH1];
__device__ float g_ydag_pr[MAX_D * NH1];
__device__ int   g_off[MAX_D + 1];
__device__ int   g_dagid[MAX_N];
__device__ float g_bsum[MAX_BLK];
__device__ float g_total;

// ---------------- helpers ----------------
__device__ __forceinline__ u64 pack2(float lo, float hi) {
    u64 r; asm("mov.b64 %0, {%1, %2};" : "=l"(r) : "f"(lo), "f"(hi)); return r;
}
__device__ __forceinline__ void fma2(u64& d, u64 a, u64 b) {
    asm("fma.rn.f32x2 %0, %1, %2, %0;" : "+l"(d) : "l"(a), "l"(b));
}
__device__ __forceinline__ float2 unpack2(u64 v) {
    float2 f; asm("mov.b64 {%0, %1}, %2;" : "=f"(f.x), "=f"(f.y) : "l"(v)); return f;
}
__device__ __forceinline__ void cp16(void* s, const void* g) {
    unsigned sa = (unsigned)__cvta_generic_to_shared(s);
    asm volatile("cp.async.ca.shared.global [%0], [%1], 16;" :: "r"(sa), "l"(g));
}
__device__ __forceinline__ void cp_commit() { asm volatile("cp.async.commit_group;"); }
__device__ __forceinline__ void cp_wait1() { asm volatile("cp.async.wait_group 1;"); }
__device__ __forceinline__ void cp_wait0() { asm volatile("cp.async.wait_group 0;"); }

// ---------------- prep: scan + z contributions ----------------
__global__ void prep_kernel(const int* __restrict__ num_ops, const float* __restrict__ z,
                            const float* __restrict__ opW1, const float* __restrict__ opb1,
                            const float* __restrict__ prW1, const float* __restrict__ prb1,
                            int D) {
    __shared__ int s[1024];
    __shared__ float zz[DIM_E];
    int t = threadIdx.x;
    if (t < DIM_E) zz[t] = z[t];
    int v = (t < D) ? num_ops[t] : 0;
    s[t] = v;
    __syncthreads();
    for (int off = 1; off < 1024; off <<= 1) {
        int add = (t >= off) ? s[t - off] : 0;
        __syncthreads();
        s[t] += add;
        __syncthreads();
    }
    if (t < D) g_off[t + 1] = s[t];
    if (t == 0) g_off[0] = 0;

    if (t < 512) {                       // zsum: 8 threads per output
        int oi = t >> 3, sub = t & 7;
        float a = 0.f;
        if (oi < NH1) {
            const float* w = opW1 + (2 * DIM_E) * NH1 + oi;
            for (int k = sub * 32; k < sub * 32 + 32; k++) a += zz[k] * w[k * NH1];
        } else {
            int j = oi - NH1;
            const float* w = prW1 + (1 + DIM_E) * NH1 + j;
            for (int k = sub * 32; k < sub * 32 + 32; k++) a += zz[k] * w[k * NH1];
        }
        a += __shfl_down_sync(0xffffffffu, a, 4);
        a += __shfl_down_sync(0xffffffffu, a, 2);
        a += __shfl_down_sync(0xffffffffu, a, 1);
        if (sub == 0) {
            if (oi < NH1) g_zsum_op[oi] = a + opb1[oi];
            else          g_zsum_pr[oi - NH1] = a + prb1[oi - NH1];
        }
    }
}

// ---------------- ydag: per-dag y contributions + dagid fill ----------------
__global__ void ydag_kernel(const float* __restrict__ y,
                            const float* __restrict__ opW1,
                            const float* __restrict__ prW1, int D) {
    __shared__ float sy[8][DIM_E];
    int t = threadIdx.x;
    int d0 = blockIdx.x * 8;
    for (int i = t; i < 8 * DIM_E; i += 256) {
        int dl = i >> 8, k = i & 255;
        int dd = d0 + dl;
        sy[dl][k] = (dd < D) ? y[dd * DIM_E + k] : 0.f;
    }
    __syncthreads();
    int dl = t >> 5, j = t & 31;
    int d = d0 + dl;
    if (d < D) {
        const float* s = sy[dl];
        float a = 0.f, b = 0.f;
        #pragma unroll 4
        for (int k = 0; k < DIM_E; k++) {
            a += s[k] * opW1[(DIM_E + k) * NH1 + j];
            b += s[k] * prW1[(1 + k) * NH1 + j];
        }
        g_ydag_op[d * NH1 + j] = a;
        g_ydag_pr[d * NH1 + j] = b;
        int lo = g_off[d], hi = g_off[d + 1];
        for (int n = lo + j; n < hi; n += 32) g_dagid[n] = d;
    }
}

// ---------------- op branch main ----------------
__global__ __launch_bounds__(BT, 2) void op_main(
    const float* __restrict__ x,
    const float* __restrict__ opW1,
    const float* __restrict__ opW2, const float* __restrict__ opb2,
    const float* __restrict__ opW3, const float* __restrict__ opb3,
    const float* __restrict__ op_msk,
    float* __restrict__ out, int N) {
    extern __shared__ char sm[];
    u64*    sW1   = (u64*)(sm + OFF_W1);
    u64*    sW2   = (u64*)(sm + OFF_W2);
    float*  sMisc = (float*)(sm + OFF_MISC);  // [0..15]=b2 [16..31]=w3 [32..63]=init [64]=b3 [80..83]=warp sums
    float4* sX    = (float4*)(sm + OFF_X);

    const int t = threadIdx.x;
    const int base = blockIdx.x * OPB;

    // stage tile tt into buffer b (coalesced cp.async, transposed layout)
    auto stage = [&](int tt, int b) {
        float4* dst = sX + b * (4 * PL);
        #pragma unroll
        for (int u = 0; u < 16; u++) {
            int idx = t + u * BT;
            int row = idx >> 2, c4 = idx & 3;
            int rg = base + row; if (rg > N - 1) rg = N - 1;
            cp16(&dst[c4 * PL + row], x + (size_t)rg * DIM_E + tt * KT + c4 * 4);
        }
    };

    stage(0, 0); cp_commit();

    // weights into smem
    {
        const float4* g = (const float4*)opW1;      // rows 0..255 = x part
        float4* d = (float4*)sW1;
        #pragma unroll
        for (int i = t; i < 2048; i += BT) d[i] = g[i];
        const float4* g2 = (const float4*)opW2;
        float4* d2 = (float4*)sW2;
        for (int i = t; i < 128; i += BT) d2[i] = g2[i];
        if (t < NH2) { sMisc[t] = opb2[t]; sMisc[16 + t] = opW3[t]; }
        if (t < NH1) sMisc[32 + t] = g_zsum_op[t];
        if (t == 0) sMisc[64] = opb3[0];
    }
    stage(1, 1); cp_commit();
    cp_wait1();
    __syncthreads();   // buf0 + weights ready

    // acc init from ydag + zsum
    int nidx[4];
    u64 acc[4][16];
    #pragma unroll
    for (int i = 0; i < 4; i++) {
        int n = base + t + i * BT;
        nidx[i] = n;
        int nc = n < N ? n : N - 1;
        int dag = g_dagid[nc];
        const float* yv = g_ydag_op + dag * NH1;
        #pragma unroll
        for (int j = 0; j < 16; j++)
            acc[i][j] = pack2(yv[2 * j] + sMisc[32 + 2 * j], yv[2 * j + 1] + sMisc[33 + 2 * j]);
    }

    for (int tt = 0; tt < NTILE; tt++) {
        const float4* bx = sX + (tt & 1) * (4 * PL);
        #pragma unroll 1
        for (int k4 = 0; k4 < 4; k4++) {
            float4 xv[4];
            #pragma unroll
            for (int i = 0; i < 4; i++) xv[i] = bx[k4 * PL + t + i * BT];
            #pragma unroll
            for (int kk = 0; kk < 4; kk++) {
                u64 xx[4];
                #pragma unroll
                for (int i = 0; i < 4; i++) {
                    float v = (kk == 0) ? xv[i].x : (kk == 1) ? xv[i].y : (kk == 2) ? xv[i].z : xv[i].w;
                    xx[i] = pack2(v, v);
                }
                const u64* w = sW1 + (tt * KT + k4 * 4 + kk) * 16;
                #pragma unroll
                for (int j = 0; j < 16; j++) {
                    u64 wv = w[j];
                    fma2(acc[0][j], xx[0], wv);
                    fma2(acc[1][j], xx[1], wv);
                    fma2(acc[2][j], xx[2], wv);
                    fma2(acc[3][j], xx[3], wv);
                }
            }
        }
        __syncthreads();                          // done reading buf[tt&1]
        if (tt + 2 < NTILE) { stage(tt + 2, tt & 1); cp_commit(); }
        if (tt + 1 < NTILE) {
            if (tt + 2 < NTILE) cp_wait1(); else cp_wait0();
            __syncthreads();                      // buf[(tt+1)&1] ready
        }
    }

    // epilogue per op
    float esum = 0.f;
    #pragma unroll
    for (int i = 0; i < 4; i++) {
        float h1[NH1];
        #pragma unroll
        for (int j = 0; j < 16; j++) {
            float2 f = unpack2(acc[i][j]);
            h1[2 * j] = fmaxf(f.x, 0.f);
            h1[2 * j + 1] = fmaxf(f.y, 0.f);
        }
        u64 a2[8];
        #pragma unroll
        for (int j = 0; j < 8; j++) a2[j] = pack2(sMisc[2 * j], sMisc[2 * j + 1]);
        #pragma unroll
        for (int k = 0; k < NH1; k++) {
            u64 hk = pack2(h1[k], h1[k]);
            const u64* w2 = sW2 + k * 8;
            #pragma unroll
            for (int j = 0; j < 8; j++) fma2(a2[j], hk, w2[j]);
        }
        float o = sMisc[64];
        #pragma unroll
        for (int j = 0; j < 8; j++) {
            float2 f = unpack2(a2[j]);
            o += fmaxf(f.x, 0.f) * sMisc[16 + 2 * j] + fmaxf(f.y, 0.f) * sMisc[17 + 2 * j];
        }
        if (nidx[i] < N) {
            float logit = o - (1.0f - op_msk[nidx[i]]) * 1000.0f;
            float e = expf(logit);    // masked underflows to exactly 0
            out[nidx[i]] = e;
            esum += e;
        }
    }

    // deterministic block sum
    float v = esum;
    v += __shfl_down_sync(0xffffffffu, v, 16);
    v += __shfl_down_sync(0xffffffffu, v, 8);
    v += __shfl_down_sync(0xffffffffu, v, 4);
    v += __shfl_down_sync(0xffffffffu, v, 2);
    v += __shfl_down_sync(0xffffffffu, v, 1);
    if ((t & 31) == 0) sMisc[80 + (t >> 5)] = v;
    __syncthreads();
    if (t == 0) g_bsum[blockIdx.x] = sMisc[80] + sMisc[81] + sMisc[82] + sMisc[83];
}

// ---------------- reduce block sums ----------------
__global__ void reduce_kernel(int nb) {
    __shared__ float s[512];
    int t = threadIdx.x;
    float a = 0.f;
    for (int i = t; i < nb; i += 512) a += g_bsum[i];
    s[t] = a;
    __syncthreads();
    for (int off = 256; off > 0; off >>= 1) {
        if (t < off) s[t] += s[t + off];
        __syncthreads();
    }
    if (t == 0) g_total = s[0];
}

// ---------------- normalize ops (float4) ----------------
__global__ void scale_kernel(float* __restrict__ out, int N) {
    float inv = 1.0f / g_total;
    int i = blockIdx.x * blockDim.x + threadIdx.x;
    int N4 = N >> 2;
    float4* o4 = (float4*)out;
    if (i < N4) {
        float4 v = o4[i];
        v.x *= inv; v.y *= inv; v.z *= inv; v.w *= inv;
        o4[i] = v;
    }
    if (i == 0) for (int k = N4 * 4; k < N; k++) out[k] *= inv;
}

// ---------------- prlvl branch: 4 dags/block ----------------
__global__ void prlvl_kernel(const float* __restrict__ prW1,
                             const float* __restrict__ prW2, const float* __restrict__ prb2,
                             const float* __restrict__ prW3, const float* __restrict__ prb3,
                             const float* __restrict__ msk,
                             float* __restrict__ out, int D, int W, int out_off) {
    __shared__ float sW2[NH1 * NH2];
    __shared__ float sB2[NH2], sW3[NH2], sRow0[NH1];
    __shared__ float sBase[4][NH1];
    __shared__ float red[4][64];
    int t = threadIdx.x;
    int d0 = blockIdx.x * 4;
    for (int i = t; i < NH1 * NH2; i += 256) sW2[i] = prW2[i];
    if (t < NH2) { sB2[t] = prb2[t]; sW3[t] = prW3[t]; }
    if (t < NH1) sRow0[t] = prW1[t];
    if (t < 128) {
        int dl = t >> 5, j = t & 31;
        int d = d0 + dl;
        sBase[dl][j] = (d < D) ? g_ydag_pr[d * NH1 + j] + g_zsum_pr[j] : 0.f;
    }
    __syncthreads();
    int dl = t >> 6, w = t & 63;
    int d = d0 + dl;
    float e = 0.f;
    if (d < D && w < W) {
        float lim = (float)(w + 1);
        float h2[NH2];
        #pragma unroll
        for (int j = 0; j < NH2; j++) h2[j] = sB2[j];
        #pragma unroll
        for (int k = 0; k < NH1; k++) {
            float h = fmaxf(sBase[dl][k] + lim * sRow0[k], 0.f);
            #pragma unroll
            for (int j = 0; j < NH2; j++) h2[j] += h * sW2[k * NH2 + j];
        }
        float o = prb3[0];
        #pragma unroll
        for (int j = 0; j < NH2; j++) o += fmaxf(h2[j], 0.f) * sW3[j];
        float logit = o - (1.0f - msk[d * W + w]) * 1000.0f;
        e = expf(logit);
    }
    red[dl][w] = e;
    __syncthreads();
    for (int off = 32; off > 0; off >>= 1) {
        if (w < off) red[dl][w] += red[dl][w + off];
        __syncthreads();
    }
    if (d < D && w < W) out[out_off + d * W + w] = e / red[dl][0];
}

// ---------------- launch ----------------
extern "C" void kernel_launch(void* const* d_in, const int* in_sizes, int n_in,
                              void* d_out, int out_size) {
    const int o = (n_in >= 20) ? 3 : 1;

    const int*   num_ops = (const int*)d_in[0];
    const float* x       = (const float*)d_in[o + 0];
    const float* y       = (const float*)d_in[o + 1];
    const float* z       = (const float*)d_in[o + 2];
    const float* op_msk  = (const float*)d_in[o + 3];
    const float* pr_msk  = (const float*)d_in[o + 4];
    const float* opW1 = (const float*)d_in[o + 5];
    const float* opb1 = (const float*)d_in[o + 6];
    const float* opW2 = (const float*)d_in[o + 7];
    const float* opb2 = (const float*)d_in[o + 8];
    const float* opW3 = (const float*)d_in[o + 9];
    const float* opb3 = (const float*)d_in[o + 10];
    const float* prW1 = (const float*)d_in[o + 11];
    const float* prb1 = (const float*)d_in[o + 12];
    const float* prW2 = (const float*)d_in[o + 13];
    const float* prb2 = (const float*)d_in[o + 14];
    const float* prW3 = (const float*)d_in[o + 15];
    const float* prb3 = (const float*)d_in[o + 16];

    const int D = in_sizes[0];
    const int N = in_sizes[o + 3];
    const int W = in_sizes[o + 4] / D;
    float* out = (float*)d_out;

    cudaFuncSetAttribute(op_main, cudaFuncAttributeMaxDynamicSharedMemorySize, SMEM_SZ);

    prep_kernel<<<1, 1024>>>(num_ops, z, opW1, opb1, prW1, prb1, D);
    ydag_kernel<<<(D + 7) / 8, 256>>>(y, opW1, prW1, D);

    int nb = (N + OPB - 1) / OPB;
    op_main<<<nb, BT, SMEM_SZ>>>(x, opW1, opW2, opb2, opW3, opb3, op_msk, out, N);
    reduce_kernel<<<1, 512>>>(nb);
    scale_kernel<<<((N >> 2) + 255) / 256, 256>>>(out, N);

    prlvl_kernel<<<(D + 3) / 4, 256>>>(prW1, prW2, prb2, prW3, prb3, pr_msk, out, D, W, N);

    (void)out_size; (void)n_in;
}